// round 8
// baseline (speedup 1.0000x reference)
#include <cuda_runtime.h>

#define TLEN 200
#define SP   36
#define BMP  20

// dynamic smem offsets (in floats)
#define O_SA   0
#define O_SAT  1152
#define O_SC   2304
#define O_SG   3456
#define O_SGT  4608
#define O_SCQ  5760
#define O_SSR  6912
#define O_SIG  8064
#define O_SPR  9216
#define O_CSB  10368
#define O_TM   11520
#define O_KM   12672
#define O_SBM  13824   // 32*20 = 640
#define O_PROW 14464   // [2][2][68]
#define O_FCOL 14736   // [2][2][34]
#define O_MU   14872
#define O_MUPR 14904
#define O_RV   14936
#define O_YV   14968   // [2][32]
#define O_UV   15032   // [2][16]
#define O_MV   15064   // [2]
#define SMEM_FLOATS 15072
#define SMEM_BYTES  (SMEM_FLOATS*4)

#define DUP2(d,s)   asm("mov.b64 %0, {%1,%1};" : "=l"(d) : "f"(s))
#define FMA2(d,a,b) asm("fma.rn.f32x2 %0, %1, %2, %0;" : "+l"(d) : "l"(a), "l"(b))
#define ADD2(d,a)   asm("add.rn.f32x2 %0, %0, %1;" : "+l"(d) : "l"(a))

__device__ __forceinline__ float2 lo2(unsigned long long u) {
    float2 f;
    f.x = __uint_as_float((unsigned)u);
    f.y = __uint_as_float((unsigned)(u >> 32));
    return f;
}

// NN 32x32x32 matmul, thread computes rows (ty, ty+16) x cols [4tx,4tx+4) via f32x2.
__device__ __forceinline__ void mm24(const float* X, const float* Y,
                                     int ty, int tx,
                                     unsigned long long& a01, unsigned long long& a23,
                                     unsigned long long& b01, unsigned long long& b23)
{
    a01 = a23 = b01 = b23 = 0ULL;
    #pragma unroll
    for (int k4 = 0; k4 < 8; ++k4) {
        float4 x0 = *(const float4*)(X + ty*SP + 4*k4);
        float4 x1 = *(const float4*)(X + (ty+16)*SP + 4*k4);
        #pragma unroll
        for (int kk = 0; kk < 4; ++kk) {
            ulonglong2 y2 = *(const ulonglong2*)(Y + (4*k4+kk)*SP + 4*tx);
            float xs0 = (kk==0)?x0.x:(kk==1)?x0.y:(kk==2)?x0.z:x0.w;
            float xs1 = (kk==0)?x1.x:(kk==1)?x1.y:(kk==2)?x1.z:x1.w;
            unsigned long long xd0, xd1;
            DUP2(xd0, xs0);
            DUP2(xd1, xs1);
            FMA2(a01, xd0, y2.x);
            FMA2(a23, xd0, y2.y);
            FMA2(b01, xd1, y2.x);
            FMA2(b23, xd1, y2.y);
        }
    }
}

__global__ __launch_bounds__(256, 2)
void kf_kernel(const float* __restrict__ Yg, const float* __restrict__ Ug,
               const float* __restrict__ maskg, const float* __restrict__ Ag,
               const float* __restrict__ Bmg, const float* __restrict__ Cg,
               const float* __restrict__ mu0g, const float* __restrict__ Sig0g,
               const float* __restrict__ Qg, const float* __restrict__ Rg,
               float* __restrict__ mf, float* __restrict__ Sf,
               float* __restrict__ mp, float* __restrict__ Sp)
{
    extern __shared__ float dyn[];
    float* sA  = dyn + O_SA;
    float* sAT = dyn + O_SAT;
    float* sC  = dyn + O_SC;
    float* sG  = dyn + O_SG;
    float* sGT = dyn + O_SGT;
    float* sCQ = dyn + O_SCQ;
    float* sSR = dyn + O_SSR;
    float* Sig = dyn + O_SIG;
    float* Spr = dyn + O_SPR;
    float* CSb = dyn + O_CSB;
    float* Tm  = dyn + O_TM;
    float* Km  = dyn + O_KM;
    float* sBm = dyn + O_SBM;
    float* PR  = dyn + O_PROW;
    float* FC  = dyn + O_FCOL;
    float* mu   = dyn + O_MU;
    float* mupr = dyn + O_MUPR;
    float* rv   = dyn + O_RV;
    float* YV   = dyn + O_YV;
    float* UV   = dyn + O_UV;
    float* MV   = dyn + O_MV;

    const int tid  = threadIdx.x;
    const int b    = blockIdx.x;
    const int mtx  = tid & 7;            // A-group matmul (tid<128)
    const int mty  = tid >> 3;
    const int wt   = tid - 128;          // B-group matmul (tid>=128)
    const int mtx2 = wt & 7;
    const int mty2 = wt >> 3;
    const int scol = tid & 15;           // solve layout
    const int srow = tid >> 4;

    const long long btb = (long long)b * TLEN;

    // ---- pre-a: load constants, init state, stage t=0 inputs ----
    for (int e = tid; e < 1024; e += 256) {
        int i = e >> 5, j = e & 31;
        float a = Ag[e], c = Cg[e];
        sA [i*SP+j] = a;  sAT[j*SP+i] = a;
        sC [i*SP+j] = c;  CSb[j*SP+i] = c;       // CSb temporarily holds C^T
        Sig[i*SP+j] = Sig0g[e];
        Tm [i*SP+j] = Qg[e];                      // Tm temporarily holds Q
    }
    for (int e = tid; e < 512; e += 256) sBm[(e>>4)*BMP + (e&15)] = Bmg[e];
    if (tid < 32) { mu[tid] = mu0g[tid]; YV[tid] = Yg[btb*32 + tid]; }
    else if (tid < 48) UV[tid-32] = Ug[btb*16 + (tid-32)];
    else if (tid == 48) MV[0] = maskg[btb];
    __syncthreads();

    // ---- pre-b: G = C*A (store sG, sGT), CQ = C*Q (store sCQ) ----
    if (tid < 128) {
        unsigned long long a01,a23,b01,b23;
        mm24(sC, sA, mty, mtx, a01,a23,b01,b23);
        *(ulonglong2*)(sG + mty*SP + 4*mtx)      = make_ulonglong2(a01,a23);
        *(ulonglong2*)(sG + (mty+16)*SP + 4*mtx) = make_ulonglong2(b01,b23);
        float2 A01=lo2(a01),A23=lo2(a23),B01f=lo2(b01),B23f=lo2(b23);
        sGT[(4*mtx+0)*SP + mty] = A01.x;  sGT[(4*mtx+1)*SP + mty] = A01.y;
        sGT[(4*mtx+2)*SP + mty] = A23.x;  sGT[(4*mtx+3)*SP + mty] = A23.y;
        sGT[(4*mtx+0)*SP + mty+16] = B01f.x;  sGT[(4*mtx+1)*SP + mty+16] = B01f.y;
        sGT[(4*mtx+2)*SP + mty+16] = B23f.x;  sGT[(4*mtx+3)*SP + mty+16] = B23f.y;
        mm24(sC, Tm, mty, mtx, a01,a23,b01,b23);
        *(ulonglong2*)(sCQ + mty*SP + 4*mtx)      = make_ulonglong2(a01,a23);
        *(ulonglong2*)(sCQ + (mty+16)*SP + 4*mtx) = make_ulonglong2(b01,b23);
    }
    __syncthreads();

    // ---- pre-c: SR0 = CQ*C^T + R -> sSR ----
    if (scol < 8) {
        unsigned long long a01,a23,b01,b23;
        mm24(sCQ, CSb, srow, scol, a01,a23,b01,b23);
        ulonglong2 r0 = __ldg((const ulonglong2*)(Rg + srow*32 + 4*scol));
        ulonglong2 r1 = __ldg((const ulonglong2*)(Rg + (srow+16)*32 + 4*scol));
        ADD2(a01, r0.x); ADD2(a23, r0.y); ADD2(b01, r1.x); ADD2(b23, r1.y);
        *(ulonglong2*)(sSR + srow*SP + 4*scol)      = make_ulonglong2(a01,a23);
        *(ulonglong2*)(sSR + (srow+16)*SP + 4*scol) = make_ulonglong2(b01,b23);
    }
    __syncthreads();

    for (int t = 0; t < TLEN; ++t) {
        const long long bt = btb + t;
        const int cur = t & 1, nxtb = cur ^ 1;
        float mun = 0.f;

        // ---- P1: T1 = A*Sig -> Tm (w0-3);  T2 = G*Sig -> Km (w4-7) ----
        if (tid < 128) {
            unsigned long long a01,a23,b01,b23;
            mm24(sA, Sig, mty, mtx, a01,a23,b01,b23);
            *(ulonglong2*)(Tm + mty*SP + 4*mtx)      = make_ulonglong2(a01,a23);
            *(ulonglong2*)(Tm + (mty+16)*SP + 4*mtx) = make_ulonglong2(b01,b23);
        } else {
            unsigned long long a01,a23,b01,b23;
            mm24(sG, Sig, mty2, mtx2, a01,a23,b01,b23);
            *(ulonglong2*)(Km + mty2*SP + 4*mtx2)      = make_ulonglong2(a01,a23);
            *(ulonglong2*)(Km + (mty2+16)*SP + 4*mtx2) = make_ulonglong2(b01,b23);
        }
        __syncthreads();

        // ---- P2: Spr = T1*A^T + Q (w0-3, +Sp);  CS = T2*A^T + CQ -> CSb (w4-7) ----
        if (tid < 128) {
            unsigned long long a01,a23,b01,b23;
            mm24(Tm, sAT, mty, mtx, a01,a23,b01,b23);
            ulonglong2 qa = __ldg((const ulonglong2*)(Qg + mty*32 + 4*mtx));
            ulonglong2 qb = __ldg((const ulonglong2*)(Qg + (mty+16)*32 + 4*mtx));
            ADD2(a01, qa.x); ADD2(a23, qa.y); ADD2(b01, qb.x); ADD2(b23, qb.y);
            *(ulonglong2*)(Spr + mty*SP + 4*mtx)      = make_ulonglong2(a01,a23);
            *(ulonglong2*)(Spr + (mty+16)*SP + 4*mtx) = make_ulonglong2(b01,b23);
            *(ulonglong2*)(Sp + bt*1024 + mty*32 + 4*mtx)      = make_ulonglong2(a01,a23);
            *(ulonglong2*)(Sp + bt*1024 + (mty+16)*32 + 4*mtx) = make_ulonglong2(b01,b23);
        } else {
            unsigned long long a01,a23,b01,b23;
            mm24(Km, sAT, mty2, mtx2, a01,a23,b01,b23);
            ulonglong2 ca = *(const ulonglong2*)(sCQ + mty2*SP + 4*mtx2);
            ulonglong2 cb = *(const ulonglong2*)(sCQ + (mty2+16)*SP + 4*mtx2);
            ADD2(a01, ca.x); ADD2(a23, ca.y); ADD2(b01, cb.x); ADD2(b23, cb.y);
            *(ulonglong2*)(CSb + mty2*SP + 4*mtx2)      = make_ulonglong2(a01,a23);
            *(ulonglong2*)(CSb + (mty2+16)*SP + 4*mtx2) = make_ulonglong2(b01,b23);
        }
        __syncthreads();

        // ---- P3': S_raw = T2*G^T -> Tm (w0-3); mu_pred + r (w7); stage t+1 (w4,w5) ----
        if (tid < 128) {
            unsigned long long a01,a23,b01,b23;
            mm24(Km, sGT, mty, mtx, a01,a23,b01,b23);
            *(ulonglong2*)(Tm + mty*SP + 4*mtx)      = make_ulonglong2(a01,a23);
            *(ulonglong2*)(Tm + (mty+16)*SP + 4*mtx) = make_ulonglong2(b01,b23);
        } else if (tid >= 224) {
            int l = tid - 224;
            float acc = 0.f;
            #pragma unroll
            for (int c = 0; c < 8; ++c) {
                float4 a = *(const float4*)(sA + l*SP + 4*c);
                float4 m = *(const float4*)(mu + 4*c);
                acc += a.x*m.x + a.y*m.y + a.z*m.z + a.w*m.w;
            }
            #pragma unroll
            for (int c = 0; c < 4; ++c) {
                float4 a = *(const float4*)(sBm + l*BMP + 4*c);
                float4 m = *(const float4*)(UV + cur*16 + 4*c);
                acc += a.x*m.x + a.y*m.y + a.z*m.z + a.w*m.w;
            }
            mupr[l] = acc;
            mp[bt*32 + l] = acc;
            __syncwarp();
            float racc = YV[cur*32 + l];
            #pragma unroll
            for (int c = 0; c < 8; ++c) {
                float4 a = *(const float4*)(sC + l*SP + 4*c);
                float4 m = *(const float4*)(mupr + 4*c);
                racc -= a.x*m.x + a.y*m.y + a.z*m.z + a.w*m.w;
            }
            rv[l] = racc;
        } else if (t + 1 < TLEN) {
            if (tid < 144)       UV[nxtb*16 + (tid-128)] = Ug[(bt+1)*16 + (tid-128)];
            else if (tid == 144) MV[nxtb] = maskg[bt+1];
            else if (tid >= 160 && tid < 192) YV[nxtb*32 + (tid-160)] = Yg[(bt+1)*32 + (tid-160)];
        }
        __syncthreads();

        // ---- P5: augmented rows into registers (no sym, no conflicts); seed snapshots ----
        float4 e0, e1;
        if (scol < 8) {
            const int j0 = 4*scol;
            float4 t0 = *(const float4*)(Tm + srow*SP + j0);
            float4 t1 = *(const float4*)(Tm + (srow+16)*SP + j0);
            float4 s0 = *(const float4*)(sSR + srow*SP + j0);
            float4 s1 = *(const float4*)(sSR + (srow+16)*SP + j0);
            e0.x = t0.x+s0.x; e0.y = t0.y+s0.y; e0.z = t0.z+s0.z; e0.w = t0.w+s0.w;
            e1.x = t1.x+s1.x; e1.y = t1.y+s1.y; e1.z = t1.z+s1.z; e1.w = t1.w+s1.w;
        } else {
            const int j0 = 4*(scol-8);
            e0 = *(const float4*)(CSb + srow*SP + j0);
            e1 = *(const float4*)(CSb + (srow+16)*SP + j0);
        }
        if (srow == 0) *(float4*)(PR + 0*68 + 4*scol) = e0;
        if (srow == 1) *(float4*)(PR + 1*68 + 4*scol) = e0;
        if (scol == 0) {
            FC[0*34 + srow]      = e0.x;  FC[1*34 + srow]      = e0.y;
            FC[0*34 + srow + 16] = e1.x;  FC[1*34 + srow + 16] = e1.y;
        }
        __syncthreads();

        // ---- P6: paired-pivot Gauss-Jordan, 16 rounds; K write merged into round 15 ----
        #pragma unroll
        for (int r = 0; r < 16; ++r) {
            const int rb = r & 1, nb = rb ^ 1;
            const int p0 = 2*r, p1 = 2*r + 1;
            const float* PRc = PR + (rb*2)*68;
            const float* FCc = FC + (rb*2)*34;
            float4 P0 = *(const float4*)(PRc + 4*scol);
            float4 P1 = *(const float4*)(PRc + 68 + 4*scol);
            float B00 = PRc[p0],      B01v = PRc[p1];
            float B10 = PRc[68 + p0], B11v = PRc[68 + p1];
            float det = B00*B11v - B01v*B10;
            float dinv;
            asm("rcp.approx.f32 %0, %1;" : "=f"(dinv) : "f"(det));
            float i00 =  B11v*dinv, i01 = -B01v*dinv;
            float i10 = -B10 *dinv, i11 =  B00 *dinv;
            float4 W0, W1;
            W0.x = i00*P0.x + i01*P1.x;  W0.y = i00*P0.y + i01*P1.y;
            W0.z = i00*P0.z + i01*P1.z;  W0.w = i00*P0.w + i01*P1.w;
            W1.x = i10*P0.x + i11*P1.x;  W1.y = i10*P0.y + i11*P1.y;
            W1.z = i10*P0.z + i11*P1.z;  W1.w = i10*P0.w + i11*P1.w;
            float g00 = FCc[srow]           - ((srow    == p0) ? 1.f : 0.f);
            float g01 = FCc[34 + srow]      - ((srow    == p1) ? 1.f : 0.f);
            float g10 = FCc[srow + 16]      - ((srow+16 == p0) ? 1.f : 0.f);
            float g11 = FCc[34 + srow + 16] - ((srow+16 == p1) ? 1.f : 0.f);
            e0.x -= g00*W0.x + g01*W1.x;  e0.y -= g00*W0.y + g01*W1.y;
            e0.z -= g00*W0.z + g01*W1.z;  e0.w -= g00*W0.w + g01*W1.w;
            e1.x -= g10*W0.x + g11*W1.x;  e1.y -= g10*W0.y + g11*W1.y;
            e1.z -= g10*W0.z + g11*W1.z;  e1.w -= g10*W0.w + g11*W1.w;
            if (r < 15) {
                const int q0 = p0 + 2, q1 = p0 + 3;
                const int cq = q0 >> 2, c0 = q0 & 3;
                float* PRn = PR + (nb*2)*68;
                float* FCn = FC + (nb*2)*34;
                if (srow      == q0) *(float4*)(PRn + 4*scol) = e0;
                if (srow + 16 == q0) *(float4*)(PRn + 4*scol) = e1;
                if (srow      == q1) *(float4*)(PRn + 68 + 4*scol) = e0;
                if (srow + 16 == q1) *(float4*)(PRn + 68 + 4*scol) = e1;
                if (scol == cq) {
                    FCn[srow]           = (c0 == 0) ? e0.x : e0.z;
                    FCn[34 + srow]      = (c0 == 0) ? e0.y : e0.w;
                    FCn[srow + 16]      = (c0 == 0) ? e1.x : e1.z;
                    FCn[34 + srow + 16] = (c0 == 0) ? e1.y : e1.w;
                }
            } else {
                // merged P7: K = mval * X^T into Km
                if (scol >= 8) {
                    const float mv = MV[cur];
                    const int a0 = 4*(scol-8);
                    Km[(a0+0)*SP + srow]    = mv*e0.x;
                    Km[(a0+1)*SP + srow]    = mv*e0.y;
                    Km[(a0+2)*SP + srow]    = mv*e0.z;
                    Km[(a0+3)*SP + srow]    = mv*e0.w;
                    Km[(a0+0)*SP + srow+16] = mv*e1.x;
                    Km[(a0+1)*SP + srow+16] = mv*e1.y;
                    Km[(a0+2)*SP + srow+16] = mv*e1.z;
                    Km[(a0+3)*SP + srow+16] = mv*e1.w;
                }
            }
            __syncthreads();
        }

        // ---- P8: Sig = Spr - K*CS (w0-3, +Sf);  mu_new (w7, +mf) ----
        if (tid < 128) {
            unsigned long long a01,a23,b01,b23;
            mm24(Km, CSb, mty, mtx, a01,a23,b01,b23);
            float2 A01 = lo2(a01), A23 = lo2(a23), B01f = lo2(b01), B23f = lo2(b23);
            float4 s0 = *(const float4*)(Spr + mty*SP + 4*mtx);
            float4 s1 = *(const float4*)(Spr + (mty+16)*SP + 4*mtx);
            float4 o0 = { s0.x - A01.x,  s0.y - A01.y,  s0.z - A23.x,  s0.w - A23.y  };
            float4 o1 = { s1.x - B01f.x, s1.y - B01f.y, s1.z - B23f.x, s1.w - B23f.y };
            *(float4*)(Sig + mty*SP + 4*mtx)      = o0;
            *(float4*)(Sig + (mty+16)*SP + 4*mtx) = o1;
            *(float4*)(Sf + bt*1024 + mty*32 + 4*mtx)      = o0;
            *(float4*)(Sf + bt*1024 + (mty+16)*32 + 4*mtx) = o1;
        } else if (tid >= 224) {
            int l = tid - 224;
            float acc = 0.f;
            #pragma unroll
            for (int c = 0; c < 8; ++c) {
                float4 a = *(const float4*)(Km + l*SP + 4*c);
                float4 m = *(const float4*)(rv + 4*c);
                acc += a.x*m.x + a.y*m.y + a.z*m.z + a.w*m.w;
            }
            mun = mupr[l] + acc;
            mu[l] = mun;
            mf[bt*32 + l] = mun;
        }
        __syncthreads();
    }
}

extern "C" void kernel_launch(void* const* d_in, const int* in_sizes, int n_in,
                              void* d_out, int out_size)
{
    const float* Y    = (const float*)d_in[0];
    const float* U    = (const float*)d_in[1];
    const float* mask = (const float*)d_in[2];
    const float* A    = (const float*)d_in[3];
    const float* Bm   = (const float*)d_in[4];
    const float* C    = (const float*)d_in[5];
    const float* mu0  = (const float*)d_in[6];
    const float* Sig0 = (const float*)d_in[7];
    const float* Q    = (const float*)d_in[8];
    const float* R    = (const float*)d_in[9];

    const int BT = in_sizes[2];
    const int B  = BT / TLEN;

    float* out = (float*)d_out;
    float* mf = out;
    float* Sf = mf + (long long)BT * 32;
    float* mp = Sf + (long long)BT * 1024;
    float* Sp = mp + (long long)BT * 32;

    cudaFuncSetAttribute(kf_kernel, cudaFuncAttributeMaxDynamicSharedMemorySize, SMEM_BYTES);
    kf_kernel<<<B, 256, SMEM_BYTES>>>(Y, U, mask, A, Bm, C, mu0, Sig0, Q, R, mf, Sf, mp, Sp);
}

// round 10
// speedup vs baseline: 1.1189x; 1.1189x over previous
#include <cuda_runtime.h>

#define TLEN 200
#define SP   36
#define BMP  20

#define DUP2(d,s)   asm("mov.b64 %0, {%1,%1};" : "=l"(d) : "f"(s))
#define FMA2(d,a,b) asm("fma.rn.f32x2 %0, %1, %2, %0;" : "+l"(d) : "l"(a), "l"(b))
#define ADD2(d,a)   asm("add.rn.f32x2 %0, %0, %1;" : "+l"(d) : "l"(a))
#define BAR1()      asm volatile("bar.sync 1, 128;" ::: "memory")

__device__ __forceinline__ float2 lo2(unsigned long long u) {
    float2 f;
    f.x = __uint_as_float((unsigned)u);
    f.y = __uint_as_float((unsigned)(u >> 32));
    return f;
}

// 4x4-tile NN 32x32x32 matmul on 64 threads (warps 0-1).
// Thread (rg=tid>>3, cg=tid&7) computes rows 4rg..4rg+3 x cols 4cg..4cg+3.
__device__ __forceinline__ void mm44(const float* X, const float* Y, int rg, int cg,
                                     unsigned long long acc[4][2])
{
    #pragma unroll
    for (int r = 0; r < 4; ++r) { acc[r][0] = 0ULL; acc[r][1] = 0ULL; }
    #pragma unroll
    for (int k4 = 0; k4 < 8; ++k4) {
        float4 x0 = *(const float4*)(X + (4*rg+0)*SP + 4*k4);
        float4 x1 = *(const float4*)(X + (4*rg+1)*SP + 4*k4);
        float4 x2 = *(const float4*)(X + (4*rg+2)*SP + 4*k4);
        float4 x3 = *(const float4*)(X + (4*rg+3)*SP + 4*k4);
        #pragma unroll
        for (int kk = 0; kk < 4; ++kk) {
            ulonglong2 y2 = *(const ulonglong2*)(Y + (4*k4+kk)*SP + 4*cg);
            float s0 = (kk==0)?x0.x:(kk==1)?x0.y:(kk==2)?x0.z:x0.w;
            float s1 = (kk==0)?x1.x:(kk==1)?x1.y:(kk==2)?x1.z:x1.w;
            float s2 = (kk==0)?x2.x:(kk==1)?x2.y:(kk==2)?x2.z:x2.w;
            float s3 = (kk==0)?x3.x:(kk==1)?x3.y:(kk==2)?x3.z:x3.w;
            unsigned long long d0,d1,d2,d3;
            DUP2(d0,s0); DUP2(d1,s1); DUP2(d2,s2); DUP2(d3,s3);
            FMA2(acc[0][0],d0,y2.x); FMA2(acc[0][1],d0,y2.y);
            FMA2(acc[1][0],d1,y2.x); FMA2(acc[1][1],d1,y2.y);
            FMA2(acc[2][0],d2,y2.x); FMA2(acc[2][1],d2,y2.y);
            FMA2(acc[3][0],d3,y2.x); FMA2(acc[3][1],d3,y2.y);
        }
    }
}

__device__ __forceinline__ float4 acc2f4(const unsigned long long a[2]) {
    float2 u = lo2(a[0]), v = lo2(a[1]);
    float4 o; o.x = u.x; o.y = u.y; o.z = v.x; o.w = v.y;
    return o;
}

__global__ __launch_bounds__(256, 2)
void kf_kernel(const float* __restrict__ Yg, const float* __restrict__ Ug,
               const float* __restrict__ maskg, const float* __restrict__ Ag,
               const float* __restrict__ Bmg, const float* __restrict__ Cg,
               const float* __restrict__ mu0g, const float* __restrict__ Sig0g,
               const float* __restrict__ Qg, const float* __restrict__ Rg,
               float* __restrict__ mf, float* __restrict__ Sf,
               float* __restrict__ mp, float* __restrict__ Sp)
{
    __shared__ __align__(16) float sA [32*SP], sAT[32*SP], sC [32*SP], sCT[32*SP];
    __shared__ __align__(16) float Sig[32*SP], Spr[32*SP], CSb[32*SP], Tm [32*SP], Km [32*SP];
    __shared__ __align__(16) float sBm[32*BMP];
    __shared__ __align__(16) float PR[2][2][68];     // pivot-row snapshots (64 cols), ping-pong
    __shared__ __align__(16) float2 FC2[2][34];      // pivot-col pairs, ping-pong
    __shared__ __align__(16) float mu[32], mupr[32], rv[32];
    __shared__ __align__(16) float YV[2][32], UV[2][16];
    __shared__ float MV[2];

    const int tid = threadIdx.x;
    const int b   = blockIdx.x;
    // matmul coords (tid<64) AND solve coords (tid<128):
    const int half = tid >> 6;          // 0: left 32 cols (S), 1: right (CS/X)
    const int idx  = tid & 63;
    const int rg   = idx >> 3;          // row group: rows 4rg..4rg+3
    const int cg   = idx & 7;           // col group: cols 4cg..4cg+3 (+32 if half)
    const int scol = cg + 8*half;       // 0..15 over the 64 aug columns

    const long long btb = (long long)b * TLEN;

    // ---- setup ----
    for (int e = tid; e < 1024; e += 256) {
        int i = e >> 5, j = e & 31;
        float a = Ag[e], c = Cg[e];
        sA [i*SP+j] = a;  sAT[j*SP+i] = a;
        sC [i*SP+j] = c;  sCT[j*SP+i] = c;
        Sig[i*SP+j] = Sig0g[e];
    }
    for (int e = tid; e < 512; e += 256) sBm[(e>>4)*BMP + (e&15)] = Bmg[e];
    if (tid < 32) { mu[tid] = mu0g[tid]; YV[0][tid] = Yg[btb*32 + tid]; }
    else if (tid < 48) UV[0][tid-32] = Ug[btb*16 + (tid-32)];
    else if (tid == 48) MV[0] = maskg[btb];

    // hoisted per-thread constants (warps 0-1): Q rows (P2) and R rows (solve seed)
    ulonglong2 qh[4];
    float4 rh[4];
    if (tid < 64) {
        #pragma unroll
        for (int r = 0; r < 4; ++r) {
            qh[r] = __ldg((const ulonglong2*)(Qg + (4*rg+r)*32 + 4*cg));
            rh[r] = __ldg((const float4*)   (Rg + (4*rg+r)*32 + 4*cg));
        }
    }
    __syncthreads();

    for (int t = 0; t < TLEN; ++t) {
        const long long bt = btb + t;
        const int cur = t & 1, nxtb = cur ^ 1;

        // ---- P1: Tm = A * Sig (warps 0-1) ----
        if (tid < 64) {
            unsigned long long acc[4][2];
            mm44(sA, Sig, rg, cg, acc);
            #pragma unroll
            for (int r = 0; r < 4; ++r)
                *(float4*)(Tm + (4*rg+r)*SP + 4*cg) = acc2f4(acc[r]);
        }
        __syncthreads();

        // ---- P2: Spr = Tm * A^T + Q (w0-1); mu_pred (w7, +mp) ----
        if (tid < 64) {
            unsigned long long acc[4][2];
            mm44(Tm, sAT, rg, cg, acc);
            #pragma unroll
            for (int r = 0; r < 4; ++r) {
                ADD2(acc[r][0], qh[r].x);
                ADD2(acc[r][1], qh[r].y);
                *(float4*)(Spr + (4*rg+r)*SP + 4*cg) = acc2f4(acc[r]);
            }
        } else if (tid >= 224) {
            int l = tid - 224;
            float acc = 0.f;
            #pragma unroll
            for (int c = 0; c < 8; ++c) {
                float4 a = *(const float4*)(sA + l*SP + 4*c);
                float4 m = *(const float4*)(mu + 4*c);
                acc += a.x*m.x + a.y*m.y + a.z*m.z + a.w*m.w;
            }
            #pragma unroll
            for (int c = 0; c < 4; ++c) {
                float4 a = *(const float4*)(sBm + l*BMP + 4*c);
                float4 m = *(const float4*)(UV[cur] + 4*c);
                acc += a.x*m.x + a.y*m.y + a.z*m.z + a.w*m.w;
            }
            mupr[l] = acc;
            mp[bt*32 + l] = acc;
        }
        __syncthreads();

        // ---- P3: CSb = C * Spr (w0-1); r = y - C mu_pred (w7) ----
        if (tid < 64) {
            unsigned long long acc[4][2];
            mm44(sC, Spr, rg, cg, acc);
            #pragma unroll
            for (int r = 0; r < 4; ++r)
                *(float4*)(CSb + (4*rg+r)*SP + 4*cg) = acc2f4(acc[r]);
        } else if (tid >= 224) {
            int l = tid - 224;
            float acc = YV[cur][l];
            #pragma unroll
            for (int c = 0; c < 8; ++c) {
                float4 a = *(const float4*)(sC + l*SP + 4*c);
                float4 m = *(const float4*)(mupr + 4*c);
                acc -= a.x*m.x + a.y*m.y + a.z*m.z + a.w*m.w;
            }
            rv[l] = acc;
        }
        __syncthreads();

        // ================== solve window ==================
        if (tid < 128) {
            float4 e[4];
            if (half == 0) {
                // fused P4: S = CS*C^T + R directly into solve registers
                unsigned long long acc[4][2];
                mm44(CSb, sCT, rg, cg, acc);
                #pragma unroll
                for (int r = 0; r < 4; ++r) {
                    float4 v = acc2f4(acc[r]);
                    v.x += rh[r].x; v.y += rh[r].y; v.z += rh[r].z; v.w += rh[r].w;
                    e[r] = v;
                }
            } else {
                #pragma unroll
                for (int r = 0; r < 4; ++r)
                    e[r] = *(const float4*)(CSb + (4*rg+r)*SP + 4*cg);
            }
            // seed snapshots for pivot pair (0,1)
            if (rg == 0) {
                *(float4*)(&PR[0][0][4*scol]) = e[0];
                *(float4*)(&PR[0][1][4*scol]) = e[1];
            }
            if (half == 0 && cg == 0) {
                #pragma unroll
                for (int r = 0; r < 4; ++r)
                    FC2[0][4*rg+r] = make_float2(e[r].x, e[r].y);
            }
            BAR1();

            // 16 paired-pivot GJ rounds
            #pragma unroll
            for (int rr = 0; rr < 16; ++rr) {
                const int rb = rr & 1, nb = rb ^ 1;
                const int p0 = 2*rr, p1 = 2*rr + 1;
                float4 P0 = *(const float4*)(&PR[rb][0][4*scol]);
                float4 P1 = *(const float4*)(&PR[rb][1][4*scol]);
                float B00 = PR[rb][0][p0], B01v = PR[rb][0][p1];
                float B10 = PR[rb][1][p0], B11v = PR[rb][1][p1];
                float det = B00*B11v - B01v*B10;
                float dinv;
                asm("rcp.approx.f32 %0, %1;" : "=f"(dinv) : "f"(det));
                float i00 =  B11v*dinv, i01 = -B01v*dinv;
                float i10 = -B10 *dinv, i11 =  B00 *dinv;
                float4 W0, W1;
                W0.x = i00*P0.x + i01*P1.x;  W0.y = i00*P0.y + i01*P1.y;
                W0.z = i00*P0.z + i01*P1.z;  W0.w = i00*P0.w + i01*P1.w;
                W1.x = i10*P0.x + i11*P1.x;  W1.y = i10*P0.y + i11*P1.y;
                W1.z = i10*P0.z + i11*P1.z;  W1.w = i10*P0.w + i11*P1.w;
                #pragma unroll
                for (int r = 0; r < 4; ++r) {
                    const int row = 4*rg + r;
                    float2 f2 = FC2[rb][row];
                    float g0 = f2.x - ((row == p0) ? 1.f : 0.f);
                    float g1 = f2.y - ((row == p1) ? 1.f : 0.f);
                    e[r].x -= g0*W0.x + g1*W1.x;
                    e[r].y -= g0*W0.y + g1*W1.y;
                    e[r].z -= g0*W0.z + g1*W1.z;
                    e[r].w -= g0*W0.w + g1*W1.w;
                }
                if (rr < 15) {
                    const int q0 = p0 + 2;
                    const int qrg = q0 >> 2, qr = q0 & 3;
                    if (rg == qrg) {
                        *(float4*)(&PR[nb][0][4*scol]) = e[qr];
                        *(float4*)(&PR[nb][1][4*scol]) = e[qr+1];
                    }
                    if (half == 0 && cg == (q0 >> 2)) {
                        const int c0 = q0 & 3;   // 0 or 2
                        #pragma unroll
                        for (int r = 0; r < 4; ++r) {
                            float a = (c0 == 0) ? e[r].x : e[r].z;
                            float bb = (c0 == 0) ? e[r].y : e[r].w;
                            FC2[nb][4*rg+r] = make_float2(a, bb);
                        }
                    }
                } else if (half == 1) {
                    // K = mval * X^T into Km
                    const float mv = MV[cur];
                    #pragma unroll
                    for (int r = 0; r < 4; ++r) {
                        Km[(4*cg+0)*SP + 4*rg+r] = mv*e[r].x;
                        Km[(4*cg+1)*SP + 4*rg+r] = mv*e[r].y;
                        Km[(4*cg+2)*SP + 4*rg+r] = mv*e[r].z;
                        Km[(4*cg+3)*SP + 4*rg+r] = mv*e[r].w;
                    }
                }
                BAR1();
            }
        } else {
            // warps 4-7: off-critical-path work during the solve
            if (tid < 192) {
                // Sp store: Spr -> Sp[bt] (64 threads x 4 float4)
                int i = tid - 128;
                #pragma unroll
                for (int s = 0; s < 4; ++s) {
                    int f = i + 64*s;                 // float4 slot 0..255
                    int row = f >> 3, c4 = f & 7;
                    float4 v = *(const float4*)(Spr + row*SP + 4*c4);
                    *(float4*)(Sp + bt*1024 + f*4) = v;
                }
            } else if (tid < 224) {
                int l = tid - 192;
                if (t + 1 < TLEN) YV[nxtb][l] = Yg[(bt+1)*32 + l];
            } else {
                int l = tid - 224;
                if (t + 1 < TLEN) {
                    if (l < 16) UV[nxtb][l] = Ug[(bt+1)*16 + l];
                    else if (l == 16) MV[nxtb] = maskg[bt+1];
                }
            }
        }
        __syncthreads();

        // ---- P8: Sig = Spr - Km*CSb (w0-1, +Sf); mu_new (w7, +mf) ----
        if (tid < 64) {
            unsigned long long acc[4][2];
            mm44(Km, CSb, rg, cg, acc);
            #pragma unroll
            for (int r = 0; r < 4; ++r) {
                float4 a = acc2f4(acc[r]);
                float4 s = *(const float4*)(Spr + (4*rg+r)*SP + 4*cg);
                float4 o = { s.x - a.x, s.y - a.y, s.z - a.z, s.w - a.w };
                *(float4*)(Sig + (4*rg+r)*SP + 4*cg) = o;
                *(float4*)(Sf + bt*1024 + (4*rg+r)*32 + 4*cg) = o;
            }
        } else if (tid >= 224) {
            int l = tid - 224;
            float acc = 0.f;
            #pragma unroll
            for (int c = 0; c < 8; ++c) {
                float4 a = *(const float4*)(Km + l*SP + 4*c);
                float4 m = *(const float4*)(rv + 4*c);
                acc += a.x*m.x + a.y*m.y + a.z*m.z + a.w*m.w;
            }
            float mun = mupr[l] + acc;
            mu[l] = mun;
            mf[bt*32 + l] = mun;
        }
        __syncthreads();
    }
}

extern "C" void kernel_launch(void* const* d_in, const int* in_sizes, int n_in,
                              void* d_out, int out_size)
{
    const float* Y    = (const float*)d_in[0];
    const float* U    = (const float*)d_in[1];
    const float* mask = (const float*)d_in[2];
    const float* A    = (const float*)d_in[3];
    const float* Bm   = (const float*)d_in[4];
    const float* C    = (const float*)d_in[5];
    const float* mu0  = (const float*)d_in[6];
    const float* Sig0 = (const float*)d_in[7];
    const float* Q    = (const float*)d_in[8];
    const float* R    = (const float*)d_in[9];

    const int BT = in_sizes[2];
    const int B  = BT / TLEN;

    float* out = (float*)d_out;
    float* mf = out;
    float* Sf = mf + (long long)BT * 32;
    float* mp = Sf + (long long)BT * 1024;
    float* Sp = mp + (long long)BT * 32;

    kf_kernel<<<B, 256>>>(Y, U, mask, A, Bm, C, mu0, Sig0, Q, R, mf, Sf, mp, Sp);
}

// round 11
// speedup vs baseline: 1.1949x; 1.0679x over previous
#include <cuda_runtime.h>

#define TLEN 200
#define SP   36
#define BMP  20

#define DUP2(d,s)   asm("mov.b64 %0, {%1,%1};" : "=l"(d) : "f"(s))
#define FMA2(d,a,b) asm("fma.rn.f32x2 %0, %1, %2, %0;" : "+l"(d) : "l"(a), "l"(b))
#define ADD2(d,a)   asm("add.rn.f32x2 %0, %0, %1;" : "+l"(d) : "l"(a))

__device__ __forceinline__ float2 lo2(unsigned long long u) {
    float2 f;
    f.x = __uint_as_float((unsigned)u);
    f.y = __uint_as_float((unsigned)(u >> 32));
    return f;
}

// NN 32x32x32 matmul on 128 threads (warps 0-3):
// thread (ty=tid>>3, tx=tid&7) computes rows (ty, ty+16) x cols 4tx..4tx+3.
__device__ __forceinline__ void mm24(const float* X, const float* Y,
                                     int ty, int tx,
                                     unsigned long long& a01, unsigned long long& a23,
                                     unsigned long long& b01, unsigned long long& b23)
{
    a01 = a23 = b01 = b23 = 0ULL;
    #pragma unroll
    for (int k4 = 0; k4 < 8; ++k4) {
        float4 x0 = *(const float4*)(X + ty*SP + 4*k4);
        float4 x1 = *(const float4*)(X + (ty+16)*SP + 4*k4);
        #pragma unroll
        for (int kk = 0; kk < 4; ++kk) {
            ulonglong2 y2 = *(const ulonglong2*)(Y + (4*k4+kk)*SP + 4*tx);
            float xs0 = (kk==0)?x0.x:(kk==1)?x0.y:(kk==2)?x0.z:x0.w;
            float xs1 = (kk==0)?x1.x:(kk==1)?x1.y:(kk==2)?x1.z:x1.w;
            unsigned long long xd0, xd1;
            DUP2(xd0, xs0);
            DUP2(xd1, xs1);
            FMA2(a01, xd0, y2.x);
            FMA2(a23, xd0, y2.y);
            FMA2(b01, xd1, y2.x);
            FMA2(b23, xd1, y2.y);
        }
    }
}

__device__ __forceinline__ float4 pack2(unsigned long long a, unsigned long long b) {
    float2 u = lo2(a), v = lo2(b);
    float4 o; o.x = u.x; o.y = u.y; o.z = v.x; o.w = v.y;
    return o;
}

__global__ __launch_bounds__(256, 2)
void kf_kernel(const float* __restrict__ Yg, const float* __restrict__ Ug,
               const float* __restrict__ maskg, const float* __restrict__ Ag,
               const float* __restrict__ Bmg, const float* __restrict__ Cg,
               const float* __restrict__ mu0g, const float* __restrict__ Sig0g,
               const float* __restrict__ Qg, const float* __restrict__ Rg,
               float* __restrict__ mf, float* __restrict__ Sf,
               float* __restrict__ mp, float* __restrict__ Sp)
{
    __shared__ __align__(16) float sA [32*SP], sAT[32*SP], sC [32*SP], sCT[32*SP];
    __shared__ __align__(16) float Sig[32*SP], Spr[32*SP], CSb[32*SP], Tm [32*SP], Km [32*SP];
    __shared__ __align__(16) float sBm[32*BMP];
    __shared__ __align__(16) float PR[2][2][68];     // pivot-row pair snapshots, ping-pong
    __shared__ __align__(16) float2 FC2[2][34];      // pivot-col pairs, ping-pong
    __shared__ __align__(16) float mu[32], mupr[32], rv[32];
    __shared__ __align__(16) float YV[2][32], UV[2][16];
    __shared__ float MV[2];

    const int tid = threadIdx.x;
    const int b   = blockIdx.x;
    const int mty = (tid & 127) >> 3;   // 0..15: rows (mty, mty+16)
    const int mtx = tid & 7;            // col group (4 cols)
    const int shalf = tid >> 7;         // solve: 0 = left 32 aug cols, 1 = right
    const int scol  = mtx + 8*shalf;    // aug col group 0..15

    const long long btb = (long long)b * TLEN;

    // ---- setup ----
    for (int e = tid; e < 1024; e += 256) {
        int i = e >> 5, j = e & 31;
        float a = Ag[e], c = Cg[e];
        sA [i*SP+j] = a;  sAT[j*SP+i] = a;
        sC [i*SP+j] = c;  sCT[j*SP+i] = c;
        Sig[i*SP+j] = Sig0g[e];
    }
    for (int e = tid; e < 512; e += 256) sBm[(e>>4)*BMP + (e&15)] = Bmg[e];
    if (tid < 32) { mu[tid] = mu0g[tid]; YV[0][tid] = Yg[btb*32 + tid]; }
    else if (tid < 48) UV[0][tid-32] = Ug[btb*16 + (tid-32)];
    else if (tid == 48) MV[0] = maskg[btb];

    // hoisted constants for warps 0-3: Q rows (P2) and R rows (solve seed)
    ulonglong2 qh0 = make_ulonglong2(0,0), qh1 = make_ulonglong2(0,0);
    float4 rh0 = {0,0,0,0}, rh1 = {0,0,0,0};
    if (tid < 128) {
        qh0 = __ldg((const ulonglong2*)(Qg + mty*32 + 4*mtx));
        qh1 = __ldg((const ulonglong2*)(Qg + (mty+16)*32 + 4*mtx));
        rh0 = __ldg((const float4*)(Rg + mty*32 + 4*mtx));
        rh1 = __ldg((const float4*)(Rg + (mty+16)*32 + 4*mtx));
    }
    __syncthreads();

    for (int t = 0; t < TLEN; ++t) {
        const long long bt = btb + t;
        const int cur = t & 1, nxtb = cur ^ 1;

        // ---- P1: Tm = A*Sig (w0-3); stage t+1 inputs (w4-5) ----
        if (tid < 128) {
            unsigned long long a01,a23,b01,b23;
            mm24(sA, Sig, mty, mtx, a01,a23,b01,b23);
            *(float4*)(Tm + mty*SP + 4*mtx)      = pack2(a01,a23);
            *(float4*)(Tm + (mty+16)*SP + 4*mtx) = pack2(b01,b23);
        } else if (t + 1 < TLEN) {
            if (tid < 160)       YV[nxtb][tid-128] = Yg[(bt+1)*32 + (tid-128)];
            else if (tid < 176)  UV[nxtb][tid-160] = Ug[(bt+1)*16 + (tid-160)];
            else if (tid == 176) MV[nxtb] = maskg[bt+1];
        }
        __syncthreads();

        // ---- P2: Spr = Tm*A^T + Q (w0-3); mu_pred (w7, +mp) ----
        if (tid < 128) {
            unsigned long long a01,a23,b01,b23;
            mm24(Tm, sAT, mty, mtx, a01,a23,b01,b23);
            ADD2(a01, qh0.x); ADD2(a23, qh0.y);
            ADD2(b01, qh1.x); ADD2(b23, qh1.y);
            *(float4*)(Spr + mty*SP + 4*mtx)      = pack2(a01,a23);
            *(float4*)(Spr + (mty+16)*SP + 4*mtx) = pack2(b01,b23);
        } else if (tid >= 224) {
            int l = tid - 224;
            float acc = 0.f;
            #pragma unroll
            for (int c = 0; c < 8; ++c) {
                float4 a = *(const float4*)(sA + l*SP + 4*c);
                float4 m = *(const float4*)(mu + 4*c);
                acc += a.x*m.x + a.y*m.y + a.z*m.z + a.w*m.w;
            }
            #pragma unroll
            for (int c = 0; c < 4; ++c) {
                float4 a = *(const float4*)(sBm + l*BMP + 4*c);
                float4 m = *(const float4*)(UV[cur] + 4*c);
                acc += a.x*m.x + a.y*m.y + a.z*m.z + a.w*m.w;
            }
            mupr[l] = acc;
            mp[bt*32 + l] = acc;
        }
        __syncthreads();

        // ---- P3: CSb = C*Spr (w0-3); rv (w7); Sp store (w4-6) ----
        if (tid < 128) {
            unsigned long long a01,a23,b01,b23;
            mm24(sC, Spr, mty, mtx, a01,a23,b01,b23);
            *(float4*)(CSb + mty*SP + 4*mtx)      = pack2(a01,a23);
            *(float4*)(CSb + (mty+16)*SP + 4*mtx) = pack2(b01,b23);
        } else if (tid >= 224) {
            int l = tid - 224;
            float acc = YV[cur][l];
            #pragma unroll
            for (int c = 0; c < 8; ++c) {
                float4 a = *(const float4*)(sC + l*SP + 4*c);
                float4 m = *(const float4*)(mupr + 4*c);
                acc -= a.x*m.x + a.y*m.y + a.z*m.z + a.w*m.w;
            }
            rv[l] = acc;
        } else {
            // warps 4-6: Sp[bt] = Spr (256 float4 slots over 96 threads)
            for (int f = tid - 128; f < 256; f += 96) {
                int row = f >> 3, c4 = f & 7;
                float4 v = *(const float4*)(Spr + row*SP + 4*c4);
                *(float4*)(Sp + bt*1024 + f*4) = v;
            }
        }
        __syncthreads();

        // ================== solve (all 256 threads, 2 rows x 4 cols each) ==================
        float4 e0, e1;
        if (shalf == 0) {
            // fused: S = CS*C^T + R directly into solve registers (warps 0-3)
            unsigned long long a01,a23,b01,b23;
            mm24(CSb, sCT, mty, mtx, a01,a23,b01,b23);
            e0 = pack2(a01,a23);
            e1 = pack2(b01,b23);
            e0.x += rh0.x; e0.y += rh0.y; e0.z += rh0.z; e0.w += rh0.w;
            e1.x += rh1.x; e1.y += rh1.y; e1.z += rh1.z; e1.w += rh1.w;
        } else {
            // right half: load CS slices (warps 4-7)
            e0 = *(const float4*)(CSb + mty*SP + 4*mtx);
            e1 = *(const float4*)(CSb + (mty+16)*SP + 4*mtx);
        }
        // seed snapshots for pivot pair (0,1)
        if (mty == 0) *(float4*)(&PR[0][0][4*scol]) = e0;
        if (mty == 1) *(float4*)(&PR[0][1][4*scol]) = e0;
        if (shalf == 0 && mtx == 0) {
            FC2[0][mty]      = make_float2(e0.x, e0.y);
            FC2[0][mty + 16] = make_float2(e1.x, e1.y);
        }
        __syncthreads();

        // 16 paired-pivot Gauss-Jordan rounds
        #pragma unroll
        for (int rr = 0; rr < 16; ++rr) {
            const int rb = rr & 1, nb = rb ^ 1;
            const int p0 = 2*rr, p1 = 2*rr + 1;
            float4 P0 = *(const float4*)(&PR[rb][0][4*scol]);
            float4 P1 = *(const float4*)(&PR[rb][1][4*scol]);
            float B00 = PR[rb][0][p0], B01v = PR[rb][0][p1];
            float B10 = PR[rb][1][p0], B11v = PR[rb][1][p1];
            float det = B00*B11v - B01v*B10;
            float dinv;
            asm("rcp.approx.f32 %0, %1;" : "=f"(dinv) : "f"(det));
            float i00 =  B11v*dinv, i01 = -B01v*dinv;
            float i10 = -B10 *dinv, i11 =  B00 *dinv;
            float4 W0, W1;
            W0.x = i00*P0.x + i01*P1.x;  W0.y = i00*P0.y + i01*P1.y;
            W0.z = i00*P0.z + i01*P1.z;  W0.w = i00*P0.w + i01*P1.w;
            W1.x = i10*P0.x + i11*P1.x;  W1.y = i10*P0.y + i11*P1.y;
            W1.z = i10*P0.z + i11*P1.z;  W1.w = i10*P0.w + i11*P1.w;
            float2 f0 = FC2[rb][mty];
            float2 f1 = FC2[rb][mty + 16];
            float g00 = f0.x - ((mty      == p0) ? 1.f : 0.f);
            float g01 = f0.y - ((mty      == p1) ? 1.f : 0.f);
            float g10 = f1.x - ((mty + 16 == p0) ? 1.f : 0.f);
            float g11 = f1.y - ((mty + 16 == p1) ? 1.f : 0.f);
            e0.x -= g00*W0.x + g01*W1.x;  e0.y -= g00*W0.y + g01*W1.y;
            e0.z -= g00*W0.z + g01*W1.z;  e0.w -= g00*W0.w + g01*W1.w;
            e1.x -= g10*W0.x + g11*W1.x;  e1.y -= g10*W0.y + g11*W1.y;
            e1.z -= g10*W0.z + g11*W1.z;  e1.w -= g10*W0.w + g11*W1.w;
            if (rr < 15) {
                const int q0 = p0 + 2, q1 = p0 + 3;
                if (mty      == q0) *(float4*)(&PR[nb][0][4*scol]) = e0;
                if (mty + 16 == q0) *(float4*)(&PR[nb][0][4*scol]) = e1;
                if (mty      == q1) *(float4*)(&PR[nb][1][4*scol]) = e0;
                if (mty + 16 == q1) *(float4*)(&PR[nb][1][4*scol]) = e1;
                const int cq = q0 >> 2, c0 = q0 & 3;   // c0 in {0,2}
                if (shalf == 0 && mtx == cq) {
                    FC2[nb][mty]      = (c0 == 0) ? make_float2(e0.x, e0.y)
                                                  : make_float2(e0.z, e0.w);
                    FC2[nb][mty + 16] = (c0 == 0) ? make_float2(e1.x, e1.y)
                                                  : make_float2(e1.z, e1.w);
                }
            } else if (shalf == 1) {
                // K = mval * X^T into Km
                const float mv = MV[cur];
                const int a0 = 4*mtx;
                Km[(a0+0)*SP + mty]      = mv*e0.x;
                Km[(a0+1)*SP + mty]      = mv*e0.y;
                Km[(a0+2)*SP + mty]      = mv*e0.z;
                Km[(a0+3)*SP + mty]      = mv*e0.w;
                Km[(a0+0)*SP + mty+16]   = mv*e1.x;
                Km[(a0+1)*SP + mty+16]   = mv*e1.y;
                Km[(a0+2)*SP + mty+16]   = mv*e1.z;
                Km[(a0+3)*SP + mty+16]   = mv*e1.w;
            }
            __syncthreads();
        }

        // ---- P8: Sig = Spr - Km*CSb (w0-3, +Sf); mu_new (w7, +mf) ----
        if (tid < 128) {
            unsigned long long a01,a23,b01,b23;
            mm24(Km, CSb, mty, mtx, a01,a23,b01,b23);
            float4 a0 = pack2(a01,a23);
            float4 a1 = pack2(b01,b23);
            float4 s0 = *(const float4*)(Spr + mty*SP + 4*mtx);
            float4 s1 = *(const float4*)(Spr + (mty+16)*SP + 4*mtx);
            float4 o0 = { s0.x - a0.x, s0.y - a0.y, s0.z - a0.z, s0.w - a0.w };
            float4 o1 = { s1.x - a1.x, s1.y - a1.y, s1.z - a1.z, s1.w - a1.w };
            *(float4*)(Sig + mty*SP + 4*mtx)      = o0;
            *(float4*)(Sig + (mty+16)*SP + 4*mtx) = o1;
            *(float4*)(Sf + bt*1024 + mty*32 + 4*mtx)      = o0;
            *(float4*)(Sf + bt*1024 + (mty+16)*32 + 4*mtx) = o1;
        } else if (tid >= 224) {
            int l = tid - 224;
            float acc = 0.f;
            #pragma unroll
            for (int c = 0; c < 8; ++c) {
                float4 a = *(const float4*)(Km + l*SP + 4*c);
                float4 m = *(const float4*)(rv + 4*c);
                acc += a.x*m.x + a.y*m.y + a.z*m.z + a.w*m.w;
            }
            float mun = mupr[l] + acc;
            mu[l] = mun;
            mf[bt*32 + l] = mun;
        }
        __syncthreads();
    }
}

extern "C" void kernel_launch(void* const* d_in, const int* in_sizes, int n_in,
                              void* d_out, int out_size)
{
    const float* Y    = (const float*)d_in[0];
    const float* U    = (const float*)d_in[1];
    const float* mask = (const float*)d_in[2];
    const float* A    = (const float*)d_in[3];
    const float* Bm   = (const float*)d_in[4];
    const float* C    = (const float*)d_in[5];
    const float* mu0  = (const float*)d_in[6];
    const float* Sig0 = (const float*)d_in[7];
    const float* Q    = (const float*)d_in[8];
    const float* R    = (const float*)d_in[9];

    const int BT = in_sizes[2];
    const int B  = BT / TLEN;

    float* out = (float*)d_out;
    float* mf = out;
    float* Sf = mf + (long long)BT * 32;
    float* mp = Sf + (long long)BT * 1024;
    float* Sp = mp + (long long)BT * 32;

    kf_kernel<<<B, 256>>>(Y, U, mask, A, Bm, C, mu0, Sig0, Q, R, mf, Sf, mp, Sp);
}